// round 15
// baseline (speedup 1.0000x reference)
#include <cuda_runtime.h>
#include <stdint.h>

#define NPTS  256
#define DIM   256
#define KNN   16
#define NB    128       // 2 rows/block, 512 threads (h=0/1 halves), independent blocks
#define EPSV  1e-12f
#define CHUNK 32        // dims staged per tile
#define NCH   (DIM / CHUNK)
#define TPAD  36        // tile row stride (floats): conflict-free LDS.128 phases

__device__ float    g_part[NB];
__device__ unsigned g_done = 0;
typedef unsigned long long u64;

#define FMA2(acc, x, y) asm("fma.rn.f32x2 %0, %1, %2, %0;" : "+l"(acc) : "l"(x), "l"(y))
#define ADD2(a, b)      asm("add.rn.f32x2 %0, %0, %1;"     : "+l"(a)   : "l"(b))

__device__ __forceinline__ unsigned warp_min_u32(unsigned v) {
    #pragma unroll
    for (int o = 16; o; o >>= 1) {
        unsigned u = __shfl_xor_sync(0xffffffffu, v, o);
        v = u < v ? u : v;
    }
    return v;
}

__global__ __launch_bounds__(512, 1)
void k_fused(const float* __restrict__ yi, const float* __restrict__ yit,
             float* __restrict__ out) {
    __shared__ __align__(16) float s_tile[NPTS * TPAD];          // 36 KB
    __shared__ __align__(16) float s_n[2][DIM];                  // normalized yi rows
    __shared__ __align__(16) float s_t[2][DIM];                  // normalized yit rows
    __shared__ float    s_iac[NPTS];       // per-column inverse norm
    __shared__ float    s_rnt[NPTS];       // per-column ||yn||^2
    __shared__ unsigned s_cand[2][NPTS];   // compacted candidate keys per half
    __shared__ int      s_wcol[2][KNN];    // winner columns by rank-1
    __shared__ float    s_wd1[2][KNN];     // winner d1 by rank-1
    __shared__ float    s_econ[2 * KNN];   // per-winner contributions
    __shared__ unsigned s_w3[16];
    __shared__ int      s_cnt[2];
    __shared__ float    red0[16], red1[16], red2[16];
    __shared__ float4   sh_par[2];   // ia, ic, rn, rt per row
    __shared__ float    sh_ds[2];    // dself per row
    __shared__ float    shred[16];
    __shared__ unsigned s_last;

    const int t   = threadIdx.x, b = blockIdx.x;
    const int h   = t >> 8;          // which row of the pair this half handles
    const int col = t & 255;
    const int w   = t >> 5, l = t & 31;
    const int row = 2 * b + h;

    if (t < 2) s_cnt[t] = 0;         // covered by Phase A's first barrier

    // ---------------- Phase A: normalize row `row` (3 sums, one reduction) ----------------
    float a = yi [row * DIM + col];
    float c = yit[row * DIM + col];
    float paa = a * a, pcc = c * c, pac = a * c;
    #pragma unroll
    for (int o = 16; o; o >>= 1) {
        paa += __shfl_down_sync(0xffffffffu, paa, o);
        pcc += __shfl_down_sync(0xffffffffu, pcc, o);
        pac += __shfl_down_sync(0xffffffffu, pac, o);
    }
    if (l == 0) { red0[w] = paa; red1[w] = pcc; red2[w] = pac; }
    __syncthreads();
    if (t == h * 256) {              // one thread per half
        float sa = 0.f, sc = 0.f, sac = 0.f;
        #pragma unroll
        for (int m = 0; m < 8; m++) {
            sa  += red0[h * 8 + m];
            sc  += red1[h * 8 + m];
            sac += red2[h * 8 + m];
        }
        float ia = 1.0f / sqrtf(sa + EPSV);
        float ic = 1.0f / sqrtf(sc + EPSV);
        float rn = sa * ia * ia, rt = sc * ic * ic;
        sh_par[h] = make_float4(ia, ic, rn, rt);
        sh_ds[h]  = 0.5f * sqrtf(fmaxf(rn + rt - 2.f * ia * ic * sac, 0.f) + EPSV);
    }
    __syncthreads();
    float4 P = sh_par[h];            // ia, ic, rn, rt of this half's row
    s_n[h][col] = a * P.x;
    s_t[h][col] = c * P.y;           // needed only by the lazy-d2 epilogue
    // (ordered before first compute by the staging barrier below)

    // ---------------- Phase B: staged fused norm + d1-only dot, register prefetch ----------------
    const float4* yi4 = (const float4*)yi;
    const ulonglong2* pn = (const ulonglong2*)s_n[h];

    const int lin0 = t,        r0i = lin0 >> 3, k0i = lin0 & 7;
    const int lin1 = 512 + t,  r1i = lin1 >> 3, k1i = lin1 & 7;
    const int lin2 = 1024 + t, r2i = lin2 >> 3, k2i = lin2 & 7;
    const int lin3 = 1536 + t, r3i = lin3 >> 3, k3i = lin3 & 7;
    const float4* gp0 = yi4 + r0i * (DIM / 4) + k0i;
    const float4* gp1 = yi4 + r1i * (DIM / 4) + k1i;
    const float4* gp2 = yi4 + r2i * (DIM / 4) + k2i;
    const float4* gp3 = yi4 + r3i * (DIM / 4) + k3i;
    float* sp0 = &s_tile[r0i * TPAD + 4 * k0i];
    float* sp1 = &s_tile[r1i * TPAD + 4 * k1i];
    float* sp2 = &s_tile[r2i * TPAD + 4 * k2i];
    float* sp3 = &s_tile[r3i * TPAD + 4 * k3i];

    u64 dnx = 0, dny = 0, ssx = 0, ssy = 0;
    const ulonglong2* tl = (const ulonglong2*)&s_tile[col * TPAD];

    float4 pf0 = gp0[0], pf1 = gp1[0], pf2 = gp2[0], pf3 = gp3[0];

    #pragma unroll
    for (int ch = 0; ch < NCH; ch++) {
        *(float4*)sp0 = pf0;  *(float4*)sp1 = pf1;
        *(float4*)sp2 = pf2;  *(float4*)sp3 = pf3;
        __syncthreads();
        if (ch + 1 < NCH) {
            pf0 = gp0[(ch + 1) * 8];  pf1 = gp1[(ch + 1) * 8];
            pf2 = gp2[(ch + 1) * 8];  pf3 = gp3[(ch + 1) * 8];
        }
        #pragma unroll
        for (int q = 0; q < 8; q++) {
            ulonglong2 v = tl[q];                // column `col` dims, conflict-free
            ulonglong2 A = pn[ch * 8 + q];       // warp-uniform -> LDS broadcast
            FMA2(dnx, A.x, v.x);  FMA2(dny, A.y, v.y);
            FMA2(ssx, v.x, v.x);  FMA2(ssy, v.y, v.y);
        }
        __syncthreads();
    }

    ADD2(dnx, dny);  ADD2(ssx, ssy);
    float nlo, nhi, slo, shi;
    asm("mov.b64 {%0, %1}, %2;" : "=f"(nlo), "=f"(nhi) : "l"(dnx));
    asm("mov.b64 {%0, %1}, %2;" : "=f"(slo), "=f"(shi) : "l"(ssx));

    float ss  = slo + shi;
    float iac = 1.0f / sqrtf(ss + EPSV);
    float rnt = ss * iac * iac;
    float d1  = 0.5f * sqrtf(fmaxf(P.z + rnt - 2.f * ((nlo + nhi) * iac), 0.f) + EPSV);
    if (h == 0) { s_iac[col] = iac; s_rnt[col] = rnt; }  // identical in both halves

    unsigned key = __float_as_uint(d1);   // positive: bit order == value order

    // ---------------- Pruned exact rank-count selection ----------------
    {
        unsigned kk = key;
        unsigned m1 = warp_min_u32(kk); if (kk == m1) kk = 0xffffffffu;
        unsigned m2 = warp_min_u32(kk); if (kk == m2) kk = 0xffffffffu;
        unsigned m3 = warp_min_u32(kk);
        if (l == 0) s_w3[w] = m3;
    }
    __syncthreads();
    unsigned T = 0;
    #pragma unroll
    for (int m = 0; m < 8; m++) {
        unsigned v = s_w3[h * 8 + m];
        T = v > T ? v : T;
    }

    bool cand = key < T;
    unsigned cmask = __ballot_sync(0xffffffffu, cand);
    int wcnt = __popc(cmask);
    int base = 0;
    if (l == 0 && wcnt) base = atomicAdd(&s_cnt[h], wcnt);
    base = __shfl_sync(0xffffffffu, base, 0);
    if (cand) s_cand[h][base + __popc(cmask & ((1u << l) - 1u))] = key;
    __syncthreads();

    if (cand) {
        int rc = 0;
        const int n = s_cnt[h];
        const unsigned* cl = s_cand[h];
        for (int j = 0; j < n; j++) rc += (cl[j] < key);
        // ranks are unique (distinct keys) -> collision-free slot write
        if (rc >= 1 && rc <= KNN) {
            s_wcol[h][rc - 1] = col;
            s_wd1 [h][rc - 1] = d1;
        }
    }
    __syncthreads();

    // ---------------- Lazy d2 epilogue: 32 warp-cooperative dots ----------------
    // warp w handles entries (w&7)*2 and (w&7)*2+1 of half h' = w>>3.
    {
        const int hp = w >> 3;
        const float rt_h = sh_par[hp].w;
        const float4* st4 = (const float4*)s_t[hp];
        #pragma unroll
        for (int j = 0; j < 2; j++) {
            int e   = ((w & 7) << 1) | j;
            int wc  = s_wcol[hp][e];
            float dw1 = s_wd1[hp][e];
            // coalesced re-read of yi[wc] (L2-resident) + s_t dot
            float4 v0 = yi4[wc * (DIM / 4) + l];
            float4 v1 = yi4[wc * (DIM / 4) + 32 + l];
            float4 a0 = st4[l];
            float4 a1 = st4[32 + l];
            float ps = v0.x * a0.x + v0.y * a0.y + v0.z * a0.z + v0.w * a0.w
                     + v1.x * a1.x + v1.y * a1.y + v1.z * a1.z + v1.w * a1.w;
            #pragma unroll
            for (int o = 16; o; o >>= 1) ps += __shfl_down_sync(0xffffffffu, ps, o);
            if (l == 0) {
                float dot = ps * s_iac[wc];
                float d2  = 0.5f * sqrtf(fmaxf(rt_h + s_rnt[wc] - 2.f * dot, 0.f) + EPSV);
                float df  = dw1 - d2;
                float e1  = df * df;
                if (e == 0) e1 += fmaxf(sh_ds[hp] + 0.6f - dw1, 0.f);  // rank-1 relu
                s_econ[hp * KNN + e] = e1;
            }
        }
    }
    __syncthreads();
    if (t == 0) {
        float s = 0.f;
        #pragma unroll
        for (int m = 0; m < 2 * KNN; m++) s += s_econ[m];
        g_part[b] = s - 2.0f * (float)KNN * 0.0025f;   // both rows' -K*T
    }

    // ---------------- last arriving block: deterministic final reduce ----------------
    __threadfence();
    __syncthreads();
    if (t == 0) s_last = atomicAdd(&g_done, 1);
    __syncthreads();
    if (s_last == NB - 1) {
        float v = (t < NB) ? *((volatile float*)&g_part[t]) : 0.f;
        #pragma unroll
        for (int o = 16; o; o >>= 1) v += __shfl_down_sync(0xffffffffu, v, o);
        if (l == 0) shred[w] = v;
        __syncthreads();
        if (t == 0) {
            float s = 0.f;
            #pragma unroll
            for (int m = 0; m < 16; m++) s += shred[m];
            out[0] = s;
            *((volatile unsigned*)&g_done) = 0;   // reset for next graph replay
        }
    }
}

extern "C" void kernel_launch(void* const* d_in, const int* in_sizes, int n_in,
                              void* d_out, int out_size) {
    const float* yi  = (const float*)d_in[0];
    const float* yit = (const float*)d_in[1];
    k_fused<<<NB, 512>>>(yi, yit, (float*)d_out);
}

// round 16
// speedup vs baseline: 1.4054x; 1.4054x over previous
#include <cuda_runtime.h>
#include <stdint.h>

#define NPTS  256
#define DIM   256
#define KNN   16
#define NB    128       // 2 rows/block, 512 threads (h=0/1 halves), independent blocks
#define EPSV  1e-12f
#define CHUNK 32        // dims staged per tile
#define NCH   (DIM / CHUNK)
#define TPAD  36        // tile row stride (floats): conflict-free LDS.128 phases
#define TILEF (NPTS * TPAD)
#define SMEM_DYN (2 * TILEF * 4)   // double-buffered tile, 73728 B

__device__ float    g_part[NB];
__device__ unsigned g_done = 0;
typedef unsigned long long u64;

#define FMA2(acc, x, y) asm("fma.rn.f32x2 %0, %1, %2, %0;" : "+l"(acc) : "l"(x), "l"(y))
#define ADD2(a, b)      asm("add.rn.f32x2 %0, %0, %1;"     : "+l"(a)   : "l"(b))

__device__ __forceinline__ unsigned warp_min_u32(unsigned v) {
    #pragma unroll
    for (int o = 16; o; o >>= 1) {
        unsigned u = __shfl_xor_sync(0xffffffffu, v, o);
        v = u < v ? u : v;
    }
    return v;
}

__global__ __launch_bounds__(512, 1)
void k_fused(const float* __restrict__ yi, const float* __restrict__ yit,
             float* __restrict__ out) {
    extern __shared__ __align__(16) float dynsmem[];             // 2 tile buffers
    __shared__ __align__(16) float s_n[2][DIM];                  // normalized yi rows
    __shared__ __align__(16) float s_t[2][DIM];                  // normalized yit rows
    __shared__ float    s_iac[NPTS];       // per-column 1/||yi_col||
    __shared__ float    s_rnt[NPTS];       // per-column ||yn_col||^2
    __shared__ unsigned s_cand[2][NPTS];   // compacted candidate keys per half
    __shared__ unsigned s_w3[16];
    __shared__ int      s_cnt[2];
    __shared__ float    red0[16], red1[16], red2[16];
    __shared__ float4   sh_par[2];   // ia, ic, rn, rt per row
    __shared__ float    sh_ds[2];    // dself per row
    __shared__ float    shred[16];
    __shared__ unsigned s_last;

    const int t   = threadIdx.x, b = blockIdx.x;
    const int h   = t >> 8;          // which row of the pair this half handles
    const int col = t & 255;
    const int w   = t >> 5, l = t & 31;
    const int row = 2 * b + h;

    if (t < 2) s_cnt[t] = 0;         // covered by Phase A's first barrier

    // ---------------- Phase A: normalize row `row` (3 sums, one reduction) ----------------
    float a = yi [row * DIM + col];
    float c = yit[row * DIM + col];
    float paa = a * a, pcc = c * c, pac = a * c;
    #pragma unroll
    for (int o = 16; o; o >>= 1) {
        paa += __shfl_down_sync(0xffffffffu, paa, o);
        pcc += __shfl_down_sync(0xffffffffu, pcc, o);
        pac += __shfl_down_sync(0xffffffffu, pac, o);
    }
    if (l == 0) { red0[w] = paa; red1[w] = pcc; red2[w] = pac; }
    __syncthreads();
    if (t == h * 256) {              // one thread per half
        float sa = 0.f, sc = 0.f, sac = 0.f;
        #pragma unroll
        for (int m = 0; m < 8; m++) {
            sa  += red0[h * 8 + m];
            sc  += red1[h * 8 + m];
            sac += red2[h * 8 + m];
        }
        float ia = 1.0f / sqrtf(sa + EPSV);
        float ic = 1.0f / sqrtf(sc + EPSV);
        float rn = sa * ia * ia, rt = sc * ic * ic;
        sh_par[h] = make_float4(ia, ic, rn, rt);
        sh_ds[h]  = 0.5f * sqrtf(fmaxf(rn + rt - 2.f * ia * ic * sac, 0.f) + EPSV);
    }
    __syncthreads();
    float4 P = sh_par[h];            // ia, ic, rn, rt of this half's row
    s_n[h][col] = a * P.x;
    s_t[h][col] = c * P.y;
    // (ordered before first compute by the prologue barrier below)

    // ---------------- Phase B: double-buffered staged dual dot, register prefetch ----------------
    const float4* yi4 = (const float4*)yi;
    const ulonglong2* pn = (const ulonglong2*)s_n[h];
    const ulonglong2* pc = (const ulonglong2*)s_t[h];

    const int lin0 = t,        r0i = lin0 >> 3, k0i = lin0 & 7;
    const int lin1 = 512 + t,  r1i = lin1 >> 3, k1i = lin1 & 7;
    const int lin2 = 1024 + t, r2i = lin2 >> 3, k2i = lin2 & 7;
    const int lin3 = 1536 + t, r3i = lin3 >> 3, k3i = lin3 & 7;
    const float4* gp0 = yi4 + r0i * (DIM / 4) + k0i;
    const float4* gp1 = yi4 + r1i * (DIM / 4) + k1i;
    const float4* gp2 = yi4 + r2i * (DIM / 4) + k2i;
    const float4* gp3 = yi4 + r3i * (DIM / 4) + k3i;
    const int so0 = r0i * TPAD + 4 * k0i;
    const int so1 = r1i * TPAD + 4 * k1i;
    const int so2 = r2i * TPAD + 4 * k2i;
    const int so3 = r3i * TPAD + 4 * k3i;
    float* const bufA = dynsmem;            // chunk even
    float* const bufB = dynsmem + TILEF;    // chunk odd

    u64 dnx = 0, dny = 0, dtx = 0, dty = 0, ssx = 0, ssy = 0;

    // prologue: stage chunk 0 into bufA
    {
        float4 pf0 = gp0[0], pf1 = gp1[0], pf2 = gp2[0], pf3 = gp3[0];
        *(float4*)(bufA + so0) = pf0;  *(float4*)(bufA + so1) = pf1;
        *(float4*)(bufA + so2) = pf2;  *(float4*)(bufA + so3) = pf3;
    }
    __syncthreads();

    #pragma unroll
    for (int ch = 0; ch < NCH; ch++) {
        float4 pf0, pf1, pf2, pf3;
        if (ch + 1 < NCH) {                       // issue next chunk's loads early
            pf0 = gp0[(ch + 1) * 8];  pf1 = gp1[(ch + 1) * 8];
            pf2 = gp2[(ch + 1) * 8];  pf3 = gp3[(ch + 1) * 8];
        }
        const float* cb = (ch & 1) ? bufB : bufA;
        const ulonglong2* tl = (const ulonglong2*)(cb + col * TPAD);
        if (h == 0) {                             // warp-uniform branch, no barriers inside
            #pragma unroll
            for (int q = 0; q < 8; q++) {
                ulonglong2 v = tl[q];
                ulonglong2 A = pn[ch * 8 + q];
                ulonglong2 C = pc[ch * 8 + q];
                FMA2(dnx, A.x, v.x);  FMA2(dny, A.y, v.y);
                FMA2(dtx, C.x, v.x);  FMA2(dty, C.y, v.y);
                FMA2(ssx, v.x, v.x);  FMA2(ssy, v.y, v.y);
            }
        } else {                                  // ss comes from h=0 via shared
            #pragma unroll
            for (int q = 0; q < 8; q++) {
                ulonglong2 v = tl[q];
                ulonglong2 A = pn[ch * 8 + q];
                ulonglong2 C = pc[ch * 8 + q];
                FMA2(dnx, A.x, v.x);  FMA2(dny, A.y, v.y);
                FMA2(dtx, C.x, v.x);  FMA2(dty, C.y, v.y);
            }
        }
        if (ch + 1 < NCH) {                       // stage next chunk into the other buffer
            float* nb = (ch & 1) ? bufA : bufB;
            *(float4*)(nb + so0) = pf0;  *(float4*)(nb + so1) = pf1;
            *(float4*)(nb + so2) = pf2;  *(float4*)(nb + so3) = pf3;
        }
        __syncthreads();                           // single barrier per chunk
    }

    ADD2(dnx, dny);  ADD2(dtx, dty);
    float nlo, nhi, tlo, thi;
    asm("mov.b64 {%0, %1}, %2;" : "=f"(nlo), "=f"(nhi) : "l"(dnx));
    asm("mov.b64 {%0, %1}, %2;" : "=f"(tlo), "=f"(thi) : "l"(dtx));

    if (h == 0) {                                  // publish per-column norm terms
        ADD2(ssx, ssy);
        float slo, shi;
        asm("mov.b64 {%0, %1}, %2;" : "=f"(slo), "=f"(shi) : "l"(ssx));
        float ss  = slo + shi;
        float ia_ = 1.0f / sqrtf(ss + EPSV);
        s_iac[col] = ia_;
        s_rnt[col] = ss * ia_ * ia_;
    }
    __syncthreads();

    float iac = s_iac[col];
    float rnt = s_rnt[col];
    float d1  = 0.5f * sqrtf(fmaxf(P.z + rnt - 2.f * ((nlo + nhi) * iac), 0.f) + EPSV);
    float d2  = 0.5f * sqrtf(fmaxf(P.w + rnt - 2.f * ((tlo + thi) * iac), 0.f) + EPSV);

    unsigned key = __float_as_uint(d1);   // positive: bit order == value order

    // ---------------- Pruned exact rank-count selection ----------------
    // T = max over this half's 8 warps of (warp 3rd-smallest key): >=24 keys <= T,
    // so key >= T implies rank >= 23 > KNN. For key < T, rank among candidates
    // equals the exact global rank.
    {
        unsigned kk = key;
        unsigned m1 = warp_min_u32(kk); if (kk == m1) kk = 0xffffffffu;
        unsigned m2 = warp_min_u32(kk); if (kk == m2) kk = 0xffffffffu;
        unsigned m3 = warp_min_u32(kk);
        if (l == 0) s_w3[w] = m3;
    }
    __syncthreads();
    unsigned T = 0;
    #pragma unroll
    for (int m = 0; m < 8; m++) {
        unsigned v = s_w3[h * 8 + m];
        T = v > T ? v : T;
    }

    bool cand = key < T;
    unsigned cmask = __ballot_sync(0xffffffffu, cand);
    int wcnt = __popc(cmask);
    int base = 0;
    if (l == 0 && wcnt) base = atomicAdd(&s_cnt[h], wcnt);
    base = __shfl_sync(0xffffffffu, base, 0);
    if (cand) s_cand[h][base + __popc(cmask & ((1u << l) - 1u))] = key;
    __syncthreads();

    int rc = 999;
    if (cand) {
        rc = 0;
        const int n = s_cnt[h];
        const unsigned* cl = s_cand[h];
        for (int j = 0; j < n; j++) rc += (cl[j] < key);
    }

    float contrib = 0.f;
    if (rc >= 1 && rc <= KNN) {
        float df = d1 - d2;
        contrib = df * df;
        if (rc == 1) contrib += fmaxf(sh_ds[h] + 0.6f - d1, 0.f);
    }

    #pragma unroll
    for (int o = 16; o; o >>= 1) contrib += __shfl_down_sync(0xffffffffu, contrib, o);
    if (l == 0) shred[w] = contrib;
    __syncthreads();
    if (t == 0) {
        float s = 0.f;
        #pragma unroll
        for (int m = 0; m < 16; m++) s += shred[m];
        g_part[b] = s - 2.0f * (float)KNN * 0.0025f;   // both rows' -K*T
    }

    // ---------------- last arriving block: deterministic final reduce ----------------
    __threadfence();
    __syncthreads();
    if (t == 0) s_last = atomicAdd(&g_done, 1);
    __syncthreads();
    if (s_last == NB - 1) {
        float v = (t < NB) ? *((volatile float*)&g_part[t]) : 0.f;
        #pragma unroll
        for (int o = 16; o; o >>= 1) v += __shfl_down_sync(0xffffffffu, v, o);
        if (l == 0) shred[w] = v;
        __syncthreads();
        if (t == 0) {
            float s = 0.f;
            #pragma unroll
            for (int m = 0; m < 16; m++) s += shred[m];
            out[0] = s;
            *((volatile unsigned*)&g_done) = 0;   // reset for next graph replay
        }
    }
}

extern "C" void kernel_launch(void* const* d_in, const int* in_sizes, int n_in,
                              void* d_out, int out_size) {
    const float* yi  = (const float*)d_in[0];
    const float* yit = (const float*)d_in[1];
    // host-side attribute set, idempotent, capture-safe
    cudaFuncSetAttribute(k_fused, cudaFuncAttributeMaxDynamicSharedMemorySize, SMEM_DYN);
    k_fused<<<NB, 512, SMEM_DYN>>>(yi, yit, (float*)d_out);
}